// round 4
// baseline (speedup 1.0000x reference)
#include <cuda_runtime.h>
#include <cuda_bf16.h>
#include <cstdint>

// ---------------------------------------------------------------------------
// Problem constants
// ---------------------------------------------------------------------------
constexpr int Bsz = 8;
constexpr int S   = 768;
constexpr int Hd  = 768;
constexpr int NH  = 12;
constexpr int NL  = 5;
constexpr int BS  = Bsz * S;                 // 6144 rows
constexpr long long HH = (long long)Hd * Hd; // 589824

typedef __nv_bfloat16 bf16;

// ---------------------------------------------------------------------------
// Scratch (static device globals)
// ---------------------------------------------------------------------------
__device__ float g_Q  [BS * Hd];
__device__ float g_K  [BS * Hd];
__device__ float g_V  [BS * Hd];
__device__ float g_ctx[BS * Hd];
__device__ float g_o  [BS * Hd];

__device__ bf16 g_hs_h [BS * Hd], g_hs_l [BS * Hd];
__device__ bf16 g_ctx_h[BS * Hd], g_ctx_l[BS * Hd];

__device__ bf16 g_inw_h[3 * Hd * Hd], g_inw_l[3 * Hd * Hd];
__device__ bf16 g_pw_h [Hd * Hd],     g_pw_l [Hd * Hd];
__device__ bf16 g_owT_h[Hd * Hd],     g_owT_l[Hd * Hd];

__device__ bf16 g_WqT_h[NL * Hd * Hd], g_WqT_l[NL * Hd * Hd];
__device__ bf16 g_WkT_h[NL * Hd * Hd], g_WkT_l[NL * Hd * Hd];
__device__ bf16 g_Wqc_h[NL * Hd * Hd], g_Wqc_l[NL * Hd * Hd];
__device__ bf16 g_Wkc_h[NL * Hd * Hd], g_Wkc_l[NL * Hd * Hd];
__device__ bf16 g_GT_h [NL * Hd * Hd], g_GT_l [NL * Hd * Hd];
__device__ bf16 g_WfT_h[NL * Hd * Hd], g_WfT_l[NL * Hd * Hd];
__device__ bf16 g_scr_h[NL * Hd * Hd], g_scr_l[NL * Hd * Hd];

__device__ float g_bqc [NL * Hd];
__device__ float g_bkc [NL * Hd];
__device__ float g_bfin[NL * Hd];

// chain nodes: normal + transposed, hi + lo
__device__ bf16 g_F_h [NL * 8 * Hd * Hd], g_F_l [NL * 8 * Hd * Hd];
__device__ bf16 g_FT_h[NL * 8 * Hd * Hd], g_FT_l[NL * 8 * Hd * Hd];
__device__ bf16 g_P1_h[NL * 4 * Hd * Hd], g_P1_l[NL * 4 * Hd * Hd];
__device__ bf16 g_QT1_h[NL * 4 * Hd * Hd], g_QT1_l[NL * 4 * Hd * Hd];
__device__ bf16 g_P2_h[NL * 2 * Hd * Hd], g_P2_l[NL * 2 * Hd * Hd];
__device__ bf16 g_QT2_h[NL * 2 * Hd * Hd], g_QT2_l[NL * 2 * Hd * Hd];
__device__ bf16 g_M_h [NL * Hd * Hd],     g_M_l [NL * Hd * Hd];
__device__ bf16 g_MT_h[NL * Hd * Hd],     g_MT_l[NL * Hd * Hd];

__device__ unsigned char g_fF [NL * 8];
__device__ unsigned char g_fP1[NL * 4];
__device__ unsigned char g_fP2[NL * 2];

// ---------------------------------------------------------------------------
// Small PTX helpers
// ---------------------------------------------------------------------------
__device__ __forceinline__ uint32_t smem_u32(const void* p) {
    return (uint32_t)__cvta_generic_to_shared(p);
}
__device__ __forceinline__ void cp16(uint32_t d, const void* s) {
    asm volatile("cp.async.cg.shared.global [%0], [%1], 16;"
                 :: "r"(d), "l"(s) : "memory");
}
__device__ __forceinline__ void cp_commit() {
    asm volatile("cp.async.commit_group;" ::: "memory");
}
template <int N>
__device__ __forceinline__ void cp_wait() {
    asm volatile("cp.async.wait_group %0;" :: "n"(N) : "memory");
}
__device__ __forceinline__ void ldsm4(uint32_t* r, uint32_t addr) {
    asm volatile("ldmatrix.sync.aligned.m8n8.x4.shared.b16 {%0,%1,%2,%3}, [%4];"
                 : "=r"(r[0]), "=r"(r[1]), "=r"(r[2]), "=r"(r[3]) : "r"(addr));
}
__device__ __forceinline__ void mma_bf16(float* d, const uint32_t* a,
                                         uint32_t b0, uint32_t b1) {
    asm volatile(
        "mma.sync.aligned.m16n8k16.row.col.f32.bf16.bf16.f32 "
        "{%0,%1,%2,%3}, {%4,%5,%6,%7}, {%8,%9}, {%0,%1,%2,%3};"
        : "+f"(d[0]), "+f"(d[1]), "+f"(d[2]), "+f"(d[3])
        : "r"(a[0]), "r"(a[1]), "r"(a[2]), "r"(a[3]), "r"(b0), "r"(b1));
}
__device__ __forceinline__ uint32_t pack_bf(bf16 a, bf16 b) {
    return (uint32_t)__bfloat16_as_ushort(a) |
           ((uint32_t)__bfloat16_as_ushort(b) << 16);
}

// ---------------------------------------------------------------------------
// GEMM config: 128x128 tile, BLK_K=32, 8 warps, 2 stages
// ---------------------------------------------------------------------------
constexpr int SKP     = 40;
constexpr int TILE_B  = 128 * SKP * 2;
constexpr int STAGE_B = 4 * TILE_B;
constexpr int GEMM_SMEM = 2 * STAGE_B;       // 81920 bytes

__device__ __forceinline__ void gemm_issue(
    const bf16* __restrict__ base, int lw, uint32_t sdst0, int kc)
{
    const bf16* g0 = base + kc * 32;
#pragma unroll
    for (int i = 0; i < 8; i++) {
        const int chunk = i * 64 + lw;
        const int row = chunk >> 2, cs = chunk & 3;
        cp16(sdst0 + row * (SKP * 2) + cs * 16,
             g0 + (long long)row * Hd + cs * 8);
    }
}

// MODE 0: fp32 out (+bias). MODE 1: bf16 hi/lo out. MODE 2: bf16 + transposed.
template <int MODE>
__device__ void gemm_core(
    const bf16* __restrict__ Ah, const bf16* __restrict__ Al,
    const bf16* __restrict__ Wh, const bf16* __restrict__ Wl,
    const float* __restrict__ bias,
    float* __restrict__ C,
    bf16* __restrict__ Ch, bf16* __restrict__ Cl,
    bf16* __restrict__ Th, bf16* __restrict__ Tl,
    int m0, int n0)
{
    extern __shared__ char dsm[];
    const int tid = threadIdx.x;
    const int wid = tid >> 5, lane = tid & 31;
    const int m_off = (wid & 3) * 32;
    const int n_off = (wid >> 2) * 64;
    const uint32_t sbase = smem_u32(dsm);

    const int ltile = tid >> 6;
    const int lw = tid & 63;
    const bf16* gbase =
        (ltile == 0) ? Ah + (long long)m0 * Hd :
        (ltile == 1) ? Al + (long long)m0 * Hd :
        (ltile == 2) ? Wh + (long long)n0 * Hd :
                       Wl + (long long)n0 * Hd;
    const uint32_t sdst_tile = ltile * TILE_B;

    gemm_issue(gbase, lw, sbase + sdst_tile, 0);             cp_commit();
    gemm_issue(gbase, lw, sbase + STAGE_B + sdst_tile, 1);   cp_commit();

    float acc[2][8][4];
#pragma unroll
    for (int mi = 0; mi < 2; mi++)
#pragma unroll
        for (int j = 0; j < 8; j++)
#pragma unroll
            for (int e = 0; e < 4; e++) acc[mi][j][e] = 0.f;

    const int r_off = ((lane >> 3) & 1) * 8 + (lane & 7);
    const int c_off = (lane >> 4) * 8;

    for (int kc = 0; kc < 24; kc++) {
        cp_wait<1>();
        __syncthreads();
        const uint32_t sb = sbase + (kc & 1) * STAGE_B;
        const uint32_t aAh = sb + (m_off + r_off) * (SKP * 2) + c_off * 2;
        const uint32_t aAl = aAh + TILE_B;
        const uint32_t aWh = sb + 2 * TILE_B + (n_off + r_off) * (SKP * 2) + c_off * 2;
        const uint32_t aWl = aWh + TILE_B;

#pragma unroll
        for (int kk = 0; kk < 2; kk++) {
            uint32_t ah[2][4], alr[2][4];
#pragma unroll
            for (int t = 0; t < 2; t++) {
                ldsm4(ah[t],  aAh + t * 16 * (SKP * 2) + kk * 32);
                ldsm4(alr[t], aAl + t * 16 * (SKP * 2) + kk * 32);
            }
#pragma unroll
            for (int u = 0; u < 4; u++) {
                uint32_t bh[4];
                ldsm4(bh, aWh + u * 16 * (SKP * 2) + kk * 32);
#pragma unroll
                for (int mi = 0; mi < 2; mi++) {
                    mma_bf16(acc[mi][2 * u],     ah[mi],  bh[0], bh[2]);
                    mma_bf16(acc[mi][2 * u + 1], ah[mi],  bh[1], bh[3]);
                    mma_bf16(acc[mi][2 * u],     alr[mi], bh[0], bh[2]);
                    mma_bf16(acc[mi][2 * u + 1], alr[mi], bh[1], bh[3]);
                }
                uint32_t bl[4];
                ldsm4(bl, aWl + u * 16 * (SKP * 2) + kk * 32);
#pragma unroll
                for (int mi = 0; mi < 2; mi++) {
                    mma_bf16(acc[mi][2 * u],     ah[mi], bl[0], bl[2]);
                    mma_bf16(acc[mi][2 * u + 1], ah[mi], bl[1], bl[3]);
                }
            }
        }
        __syncthreads();
        if (kc + 2 < 24)
            gemm_issue(gbase, lw, sbase + (kc & 1) * STAGE_B + sdst_tile, kc + 2);
        cp_commit();
    }

    // stage accumulators through SMEM (f32 [128][132])
    float* sf = (float*)dsm;
    const int g = lane >> 2, t2 = (lane & 3) * 2;
#pragma unroll
    for (int mi = 0; mi < 2; mi++)
#pragma unroll
        for (int j = 0; j < 8; j++) {
            const int r = m_off + mi * 16 + g;
            const int c = n_off + j * 8 + t2;
            sf[r * 132 + c]           = acc[mi][j][0];
            sf[r * 132 + c + 1]       = acc[mi][j][1];
            sf[(r + 8) * 132 + c]     = acc[mi][j][2];
            sf[(r + 8) * 132 + c + 1] = acc[mi][j][3];
        }
    __syncthreads();

    if (MODE == 0) {
#pragma unroll 4
        for (int i = 0; i < 16; i++) {
            const int task = i * 256 + tid;
            const int row = task >> 5, c4 = (task & 31) * 4;
            float4 v = *(float4*)&sf[row * 132 + c4];
            v.x += bias[n0 + c4 + 0];
            v.y += bias[n0 + c4 + 1];
            v.z += bias[n0 + c4 + 2];
            v.w += bias[n0 + c4 + 3];
            *(float4*)(C + (long long)(m0 + row) * Hd + n0 + c4) = v;
        }
    } else {
#pragma unroll 4
        for (int i = 0; i < 16; i++) {
            const int task = i * 256 + tid;
            const int row = task >> 5, c4 = (task & 31) * 4;
            float4 v = *(float4*)&sf[row * 132 + c4];
            bf16 h0 = __float2bfloat16(v.x), h1 = __float2bfloat16(v.y);
            bf16 h2 = __float2bfloat16(v.z), h3 = __float2bfloat16(v.w);
            bf16 l0 = __float2bfloat16(v.x - __bfloat162float(h0));
            bf16 l1 = __float2bfloat16(v.y - __bfloat162float(h1));
            bf16 l2 = __float2bfloat16(v.z - __bfloat162float(h2));
            bf16 l3 = __float2bfloat16(v.w - __bfloat162float(h3));
            const long long off = (long long)(m0 + row) * Hd + n0 + c4;
            *(uint2*)(Ch + off) = make_uint2(pack_bf(h0, h1), pack_bf(h2, h3));
            *(uint2*)(Cl + off) = make_uint2(pack_bf(l0, l1), pack_bf(l2, l3));
        }
        if (MODE == 2) {
            const int c = tid & 127;
            const int half = tid >> 7;
#pragma unroll 4
            for (int i = 0; i < 16; i++) {
                const int r4 = half * 64 + i * 4;
                float v0 = sf[(r4 + 0) * 132 + c];
                float v1 = sf[(r4 + 1) * 132 + c];
                float v2 = sf[(r4 + 2) * 132 + c];
                float v3 = sf[(r4 + 3) * 132 + c];
                bf16 h0 = __float2bfloat16(v0), h1 = __float2bfloat16(v1);
                bf16 h2 = __float2bfloat16(v2), h3 = __float2bfloat16(v3);
                bf16 l0 = __float2bfloat16(v0 - __bfloat162float(h0));
                bf16 l1 = __float2bfloat16(v1 - __bfloat162float(h1));
                bf16 l2 = __float2bfloat16(v2 - __bfloat162float(h2));
                bf16 l3 = __float2bfloat16(v3 - __bfloat162float(h3));
                const long long off = (long long)(n0 + c) * Hd + m0 + r4;
                *(uint2*)(Th + off) = make_uint2(pack_bf(h0, h1), pack_bf(h2, h3));
                *(uint2*)(Tl + off) = make_uint2(pack_bf(l0, l1), pack_bf(l2, l3));
            }
        }
    }
}

// ---------------------------------------------------------------------------
// GEMM wrappers
// ---------------------------------------------------------------------------
// final: out = ctx @ Wfin[lang] + bfin[lang]   (W operand = WfinT)
__global__ __launch_bounds__(256, 2) void k_final(
    const bf16* __restrict__ Ah, const bf16* __restrict__ Al,
    const bf16* __restrict__ WTh, const bf16* __restrict__ WTl,
    const float* __restrict__ bias, const int* __restrict__ lang,
    float* __restrict__ C)
{
    const int z = blockIdx.z;
    const int lg = __ldg(&lang[z]);
    const long long ao = (long long)z * S * Hd;
    gemm_core<0>(Ah + ao, Al + ao, WTh + (long long)lg * HH, WTl + (long long)lg * HH,
                 bias + lg * Hd, C + ao, nullptr, nullptr, nullptr, nullptr,
                 blockIdx.y * 128, blockIdx.x * 128);
}

// fused QKV: z = kind*8 + batch
__global__ __launch_bounds__(256, 2) void k_qkv(
    const bf16* __restrict__ hs_h, const bf16* __restrict__ hs_l,
    const bf16* __restrict__ Wqc_h, const bf16* __restrict__ Wqc_l,
    const float* __restrict__ bqc,
    const bf16* __restrict__ Wkc_h, const bf16* __restrict__ Wkc_l,
    const float* __restrict__ bkc,
    const bf16* __restrict__ wv_h, const bf16* __restrict__ wv_l,
    const float* __restrict__ bv,
    const int* __restrict__ lang,
    float* __restrict__ Q, float* __restrict__ K, float* __restrict__ V)
{
    const int z = blockIdx.z;
    const int kind = z >> 3, b = z & 7;
    const int lg = __ldg(&lang[b]);
    const long long ao = (long long)b * S * Hd;
    const bf16 *wh, *wl;
    const float* bias;
    float* C;
    if (kind == 0) {
        wh = Wqc_h + (long long)lg * HH; wl = Wqc_l + (long long)lg * HH;
        bias = bqc + lg * Hd; C = Q;
    } else if (kind == 1) {
        wh = Wkc_h + (long long)lg * HH; wl = Wkc_l + (long long)lg * HH;
        bias = bkc + lg * Hd; C = K;
    } else {
        wh = wv_h; wl = wv_l; bias = bv; C = V;
    }
    gemm_core<0>(hs_h + ao, hs_l + ao, wh, wl, bias, C + ao,
                 nullptr, nullptr, nullptr, nullptr,
                 blockIdx.y * 128, blockIdx.x * 128);
}

// weight combine: z = fam*NL + l;  Wqc[l] = wq @ Wq_lang[l]  (NT vs Wq_langT)
__global__ __launch_bounds__(256, 2) void k_wcomb(
    const bf16* __restrict__ inw_h, const bf16* __restrict__ inw_l,
    const bf16* __restrict__ WqT_h, const bf16* __restrict__ WqT_l,
    const bf16* __restrict__ WkT_h, const bf16* __restrict__ WkT_l,
    bf16* __restrict__ Wqc_h, bf16* __restrict__ Wqc_l,
    bf16* __restrict__ Wkc_h, bf16* __restrict__ Wkc_l)
{
    const int z = blockIdx.z;
    const int fam = z / NL, l = z % NL;
    const long long lo = (long long)l * HH;
    const bf16* Ah = inw_h + (long long)fam * HH;
    const bf16* Al = inw_l + (long long)fam * HH;
    const bf16* Wh = (fam ? WkT_h : WqT_h) + lo;
    const bf16* Wl = (fam ? WkT_l : WqT_l) + lo;
    bf16* Ch = (fam ? Wkc_h : Wqc_h) + lo;
    bf16* Cl = (fam ? Wkc_l : Wqc_l) + lo;
    gemm_core<1>(Ah, Al, Wh, Wl, nullptr, nullptr, Ch, Cl, nullptr, nullptr,
                 blockIdx.y * 128, blockIdx.x * 128);
}

// G[l] = M[l] @ proj_w^T  -> GT (+ scratch normal)
__global__ __launch_bounds__(256, 2) void k_G(
    const bf16* __restrict__ M_h, const bf16* __restrict__ M_l,
    const bf16* __restrict__ pw_h, const bf16* __restrict__ pw_l,
    bf16* __restrict__ scr_h, bf16* __restrict__ scr_l,
    bf16* __restrict__ GT_h, bf16* __restrict__ GT_l)
{
    const long long lo = (long long)blockIdx.z * HH;
    gemm_core<2>(M_h + lo, M_l + lo, pw_h, pw_l, nullptr, nullptr,
                 scr_h + lo, scr_l + lo, GT_h + lo, GT_l + lo,
                 blockIdx.y * 128, blockIdx.x * 128);
}

// Wfin[l] = out_w^T @ G[l]  -> WfinT (+ scratch normal)
__global__ __launch_bounds__(256, 2) void k_Wfin(
    const bf16* __restrict__ owT_h, const bf16* __restrict__ owT_l,
    const bf16* __restrict__ GT_h, const bf16* __restrict__ GT_l,
    bf16* __restrict__ scr_h, bf16* __restrict__ scr_l,
    bf16* __restrict__ WfT_h, bf16* __restrict__ WfT_l)
{
    const long long lo = (long long)blockIdx.z * HH;
    gemm_core<2>(owT_h, owT_l, GT_h + lo, GT_l + lo, nullptr, nullptr,
                 scr_h + lo, scr_l + lo, WfT_h + lo, WfT_l + lo,
                 blockIdx.y * 128, blockIdx.x * 128);
}

// chain level (unchanged)
__global__ __launch_bounds__(256, 2) void tc_chain(
    const bf16* __restrict__ sN_h, const bf16* __restrict__ sN_l,
    const bf16* __restrict__ sT_h, const bf16* __restrict__ sT_l,
    const unsigned char* __restrict__ fs,
    bf16* __restrict__ dN_h, bf16* __restrict__ dN_l,
    bf16* __restrict__ dT_h, bf16* __restrict__ dT_l,
    int spa, int dpa)
{
    const int z = blockIdx.z;
    const int a = z / dpa, p = z - a * dpa;
    const int li = a * spa + 2 * p;
    const unsigned char f1 = fs[li], f2 = fs[li + 1];
    const long long zo = (long long)z * HH;
    const int m0 = blockIdx.y * 128, n0 = blockIdx.x * 128;
    const int tid = threadIdx.x;

    if (f1 & f2) {
#pragma unroll 4
        for (int i = 0; i < 16; i++) {
            const int task = i * 256 + tid;
            const int row = task >> 5, c4 = (task & 31) * 4;
            const int gr = m0 + row, gc = n0 + c4;
            bf16 one = __float2bfloat16(1.f), zero = __float2bfloat16(0.f);
            bf16 h0 = (gc + 0 == gr) ? one : zero;
            bf16 h1 = (gc + 1 == gr) ? one : zero;
            bf16 h2 = (gc + 2 == gr) ? one : zero;
            bf16 h3 = (gc + 3 == gr) ? one : zero;
            const long long off = zo + (long long)gr * Hd + gc;
            uint2 hv = make_uint2(pack_bf(h0, h1), pack_bf(h2, h3));
            uint2 lv = make_uint2(0u, 0u);
            *(uint2*)(dN_h + off) = hv; *(uint2*)(dN_l + off) = lv;
            *(uint2*)(dT_h + off) = hv; *(uint2*)(dT_l + off) = lv;
        }
        return;
    }
    if (f1 | f2) {
        const long long so = (long long)(f1 ? li + 1 : li) * HH;
#pragma unroll 4
        for (int i = 0; i < 8; i++) {
            const int idx = i * 256 + tid;
            const int row = idx >> 4, c8 = (idx & 15) * 8;
            const long long doff = zo + (long long)(m0 + row) * Hd + n0 + c8;
            const long long soff = so + (long long)(m0 + row) * Hd + n0 + c8;
            *(uint4*)(dN_h + doff) = *(const uint4*)(sN_h + soff);
            *(uint4*)(dN_l + doff) = *(const uint4*)(sN_l + soff);
            *(uint4*)(dT_h + doff) = *(const uint4*)(sT_h + soff);
            *(uint4*)(dT_l + doff) = *(const uint4*)(sT_l + soff);
        }
        return;
    }
    gemm_core<2>(sN_h + (long long)li * HH, sN_l + (long long)li * HH,
                 sT_h + (long long)(li + 1) * HH, sT_l + (long long)(li + 1) * HH,
                 nullptr, nullptr,
                 dN_h + zo, dN_l + zo, dT_h + zo, dT_l + zo, m0, n0);
}

// ---------------------------------------------------------------------------
// conversions
// ---------------------------------------------------------------------------
__global__ __launch_bounds__(256) void k_conv(
    const float* __restrict__ src, bf16* __restrict__ dh, bf16* __restrict__ dl)
{
    const long long i4 = ((long long)blockIdx.x * 256 + threadIdx.x) * 4;
    float4 v = *(const float4*)(src + i4);
    bf16 h0 = __float2bfloat16(v.x), h1 = __float2bfloat16(v.y);
    bf16 h2 = __float2bfloat16(v.z), h3 = __float2bfloat16(v.w);
    bf16 l0 = __float2bfloat16(v.x - __bfloat162float(h0));
    bf16 l1 = __float2bfloat16(v.y - __bfloat162float(h1));
    bf16 l2 = __float2bfloat16(v.z - __bfloat162float(h2));
    bf16 l3 = __float2bfloat16(v.w - __bfloat162float(h3));
    *(uint2*)(dh + i4) = make_uint2(pack_bf(h0, h1), pack_bf(h2, h3));
    *(uint2*)(dl + i4) = make_uint2(pack_bf(l0, l1), pack_bf(l2, l3));
}

__device__ __forceinline__ void split_store4(
    bf16* dh, bf16* dl, long long off, float x, float y, float z, float w)
{
    bf16 h0 = __float2bfloat16(x), h1 = __float2bfloat16(y);
    bf16 h2 = __float2bfloat16(z), h3 = __float2bfloat16(w);
    bf16 l0 = __float2bfloat16(x - __bfloat162float(h0));
    bf16 l1 = __float2bfloat16(y - __bfloat162float(h1));
    bf16 l2 = __float2bfloat16(z - __bfloat162float(h2));
    bf16 l3 = __float2bfloat16(w - __bfloat162float(h3));
    *(uint2*)(dh + off) = make_uint2(pack_bf(h0, h1), pack_bf(h2, h3));
    *(uint2*)(dl + off) = make_uint2(pack_bf(l0, l1), pack_bf(l2, l3));
}

// transpose + split: dst[node][r][c] = src[node][c][r]
__global__ __launch_bounds__(256) void k_convT(
    const float* __restrict__ src, bf16* __restrict__ dh, bf16* __restrict__ dl)
{
    const int node = blockIdx.y;
    const float* sm = src + (long long)node * HH;
    const long long i4 = ((long long)blockIdx.x * 256 + threadIdx.x) * 4;
    const int r = (int)(i4 / Hd), c = (int)(i4 % Hd);
    float t0 = sm[(long long)(c + 0) * Hd + r];
    float t1 = sm[(long long)(c + 1) * Hd + r];
    float t2 = sm[(long long)(c + 2) * Hd + r];
    float t3 = sm[(long long)(c + 3) * Hd + r];
    split_store4(dh, dl, (long long)node * HH + i4, t0, t1, t2, t3);
}

// ---------------------------------------------------------------------------
// chain flags + leaf factors
// ---------------------------------------------------------------------------
__global__ void k_flags(const int* __restrict__ lang,
                        unsigned char* fF, unsigned char* fP1, unsigned char* fP2)
{
    if (threadIdx.x == 0 && blockIdx.x == 0) {
        for (int a = 0; a < NL; a++) {
            for (int j = 0; j < 8; j++) fF[a * 8 + j] = (lang[j] == a) ? 1 : 0;
            for (int p = 0; p < 4; p++)
                fP1[a * 4 + p] = fF[a * 8 + 2 * p] & fF[a * 8 + 2 * p + 1];
            for (int p = 0; p < 2; p++)
                fP2[a * 2 + p] = fP1[a * 4 + 2 * p] & fP1[a * 4 + 2 * p + 1];
        }
    }
}

__global__ __launch_bounds__(256) void k_factors(
    const float* __restrict__ alignT, const int* __restrict__ lang,
    bf16* __restrict__ Fh, bf16* __restrict__ Fl,
    bf16* __restrict__ FTh, bf16* __restrict__ FTl)
{
    const int node = blockIdx.y;
    const int a = node >> 3, j = node & 7;
    const int c = __ldg(&lang[j]);
    const long long nb = (long long)node * HH;
    const long long i4 = ((long long)blockIdx.x * 256 + threadIdx.x) * 4;
    const int r = (int)(i4 / Hd), col = (int)(i4 % Hd);

    if (c == a) {
        float v0 = (col + 0 == r) ? 1.f : 0.f;
        float v1 = (col + 1 == r) ? 1.f : 0.f;
        float v2 = (col + 2 == r) ? 1.f : 0.f;
        float v3 = (col + 3 == r) ? 1.f : 0.f;
        split_store4(Fh,  Fl,  nb + i4, v0, v1, v2, v3);
        split_store4(FTh, FTl, nb + i4, v0, v1, v2, v3);
    } else {
        const float* sm = alignT + (long long)(a * NL + c) * HH;
        float4 v = *(const float4*)(sm + i4);
        split_store4(Fh, Fl, nb + i4, v.x, v.y, v.z, v.w);
        float t0 = sm[(long long)(col + 0) * Hd + r];
        float t1 = sm[(long long)(col + 1) * Hd + r];
        float t2 = sm[(long long)(col + 2) * Hd + r];
        float t3 = sm[(long long)(col + 3) * Hd + r];
        split_store4(FTh, FTl, nb + i4, t0, t1, t2, t3);
    }
}

// ---------------------------------------------------------------------------
// bias precompute
// ---------------------------------------------------------------------------
// bqc[l][o] = sum_k wq[o][k]*bq_lang[l][k] + in_b[o]   (fam 0: q, 1: k)
__global__ void k_bias_qk(
    const float* __restrict__ in_w, const float* __restrict__ in_b,
    const float* __restrict__ bq_lang, const float* __restrict__ bk_lang,
    float* __restrict__ bqc, float* __restrict__ bkc)
{
    const int fam = blockIdx.x, l = blockIdx.y, o = threadIdx.x;
    const float* wrow = in_w + (long long)(fam * Hd + o) * Hd;
    const float* bl = (fam ? bk_lang : bq_lang) + l * Hd;
    float s = 0.f;
    for (int k = 0; k < Hd; k++) s += wrow[k] * bl[k];
    float* dst = fam ? bkc : bqc;
    dst[l * Hd + o] = s + in_b[fam * Hd + o];
}

// bfin[l][n] = sum_k out_b[k]*G[l][k][n] + proj_b[n]  (reads GT rows)
__global__ void k_bias_fin(
    const bf16* __restrict__ GT_h, const bf16* __restrict__ GT_l,
    const float* __restrict__ out_b, const float* __restrict__ proj_b,
    float* __restrict__ bfin)
{
    const int l = blockIdx.x, n = threadIdx.x;
    const bf16* rh = GT_h + (long long)l * HH + (long long)n * Hd;
    const bf16* rl = GT_l + (long long)l * HH + (long long)n * Hd;
    float s = 0.f;
    for (int k = 0; k < Hd; k++)
        s += out_b[k] * (__bfloat162float(rh[k]) + __bfloat162float(rl[k]));
    bfin[l * Hd + n] = s + proj_b[n];
}

// ---------------------------------------------------------------------------
// Flash attention (fp32 SIMT, passing since round 1)
// ---------------------------------------------------------------------------
__global__ __launch_bounds__(256) void k_attn(
    const float* __restrict__ Q, const float* __restrict__ K,
    const float* __restrict__ V, float* __restrict__ O)
{
    __shared__ float Qs[64 * 64];
    __shared__ float KP[64 * 64];
    __shared__ float Vs[64 * 64];

    const int qt = blockIdx.x, h = blockIdx.y, b = blockIdx.z;
    const int tid = threadIdx.x;
    const int ty = tid >> 4, tx = tid & 15;
    const long long qbase = ((long long)(b * S + qt * 64)) * Hd + h * 64;

#pragma unroll
    for (int u = 0; u < 4; u++) {
        const int fidx = u * 256 + tid;
        const int r = fidx >> 4;
        const int d = (fidx & 15) * 4;
        float4 v = *(const float4*)(Q + qbase + (long long)r * Hd + d);
        v.x *= 0.125f; v.y *= 0.125f; v.z *= 0.125f; v.w *= 0.125f;
        *(float4*)&Qs[r * 64 + d] = v;
    }

    float m[4], l[4], o[4][4];
#pragma unroll
    for (int i = 0; i < 4; i++) {
        m[i] = -1e30f; l[i] = 0.f;
#pragma unroll
        for (int j = 0; j < 4; j++) o[i][j] = 0.f;
    }

    for (int kt = 0; kt < S / 64; kt++) {
        const long long kbase = ((long long)(b * S + kt * 64)) * Hd + h * 64;
        __syncthreads();
#pragma unroll
        for (int u = 0; u < 4; u++) {
            const int fidx = u * 256 + tid;
            const int r = fidx >> 4;
            const int d = (fidx & 15) * 4;
            float4 kv = *(const float4*)(K + kbase + (long long)r * Hd + d);
            KP[(d + 0) * 64 + r] = kv.x;
            KP[(d + 1) * 64 + r] = kv.y;
            KP[(d + 2) * 64 + r] = kv.z;
            KP[(d + 3) * 64 + r] = kv.w;
            *(float4*)&Vs[r * 64 + d] =
                *(const float4*)(V + kbase + (long long)r * Hd + d);
        }
        __syncthreads();

        float s[4][4];
#pragma unroll
        for (int i = 0; i < 4; i++)
#pragma unroll
            for (int j = 0; j < 4; j++) s[i][j] = 0.f;

#pragma unroll
        for (int d0 = 0; d0 < 64; d0 += 4) {
            float a0[4], a1[4], a2[4], a3[4];
            *(float4*)a0 = *(const float4*)&Qs[(ty * 4 + 0) * 64 + d0];
            *(float4*)a1 = *(const float4*)&Qs[(ty * 4 + 1) * 64 + d0];
            *(float4*)a2 = *(const float4*)&Qs[(ty * 4 + 2) * 64 + d0];
            *(float4*)a3 = *(const float4*)&Qs[(ty * 4 + 3) * 64 + d0];
#pragma unroll
            for (int dd = 0; dd < 4; dd++) {
                const float b0 = KP[(d0 + dd) * 64 + tx];
                const float b1 = KP[(d0 + dd) * 64 + tx + 16];
                const float b2 = KP[(d0 + dd) * 64 + tx + 32];
                const float b3 = KP[(d0 + dd) * 64 + tx + 48];
                s[0][0] += a0[dd] * b0; s[0][1] += a0[dd] * b1;
                s[0][2] += a0[dd] * b2; s[0][3] += a0[dd] * b3;
                s[1][0] += a1[dd] * b0; s[1][1] += a1[dd] * b1;
                s[1][2] += a1[dd] * b2; s[1][3] += a1[dd] * b3;
                s[2][0] += a2[dd] * b0; s[2][1] += a2[dd] * b1;
                s[2][2] += a2[dd] * b2; s[2][3] += a2[dd] * b3;
                s[3][0] += a3[dd] * b0; s[3][1] += a3[dd] * b1;
                s[3][2] += a3[dd] * b2; s[3][3] += a3[dd] * b3;
            }
        }

        float p[4][4];
#pragma unroll
        for (int i = 0; i < 4; i++) {
            float mx = fmaxf(fmaxf(s[i][0], s[i][1]), fmaxf(s[i][2], s[i][3]));
#pragma unroll
            for (int off = 8; off >= 1; off >>= 1)
                mx = fmaxf(mx, __shfl_xor_sync(0xffffffffu, mx, off));
            const float mn = fmaxf(m[i], mx);
            const float alpha = __expf(m[i] - mn);
            m[i] = mn;
            float rs = 0.f;
#pragma unroll
            for (int j = 0; j < 4; j++) {
                p[i][j] = __expf(s[i][j] - mn);
                rs += p[i][j];
            }
#pragma unroll
            for (int off = 8; off >= 1; off >>= 1)
                rs += __shfl_xor_sync(0xffffffffu, rs, off);
            l[i] = l[i] * alpha + rs;
            o[i][0] *= alpha; o[i][1] *= alpha;
            o[i][2] *= alpha; o[i][3] *= alpha;
        }

        __syncthreads();
#pragma unroll
        for (int i = 0; i < 4; i++)
#pragma unroll
            for (int j = 0; j < 4; j++)
                KP[(ty * 4 + i) * 64 + tx + 16 * j] = p[i][j];
        __syncthreads();

#pragma unroll
        for (int k = 0; k < 64; k++) {
            const float4 v = *(const float4*)&Vs[k * 64 + tx * 4];
            const float p0 = KP[(ty * 4 + 0) * 64 + k];
            const float p1 = KP[(ty * 4 + 1) * 64 + k];
            const float p2 = KP[(ty * 4 + 2) * 64 + k];
            const float p3 = KP[(ty * 4 + 3) * 64 + k];
            o[0][0] += p0 * v.x; o[0][1] += p0 * v.y; o[0][2] += p0 * v.z; o[0][3] += p0 * v.w;
            o[1][0] += p1 * v.x; o[1][1] += p1 * v.y; o[1][2] += p1 * v.z; o[1][3] += p1 * v.w;
            o[2][0] += p2 * v.x; o[2][1] += p2 * v.y; o[2][2] += p2 * v.z; o[2][3] += p2 * v.w;
            o[3][0] += p3 * v.x; o[3][1] += p3 * v.y; o[3][2] += p3 * v.z; o[3][3] += p3 * v.w;
        }
    }

#pragma unroll
    for (int i = 0; i < 4; i++) {
        const float inv = 1.f / l[i];
        float4 v = make_float4(o[i][0] * inv, o[i][1] * inv,
                               o[i][2] * inv, o[i][3] * inv);
        *(float4*)(O + qbase + (long long)(ty * 4 + i) * Hd + tx * 4) = v;
    }
}

// ---------------------------------------------------------------------------
// Residual + LayerNorm
// ---------------------------------------------------------------------------
__global__ __launch_bounds__(256) void k_ln(
    const float* __restrict__ X, const float* __restrict__ Rres,
    const float* __restrict__ gam, const float* __restrict__ bet,
    float* __restrict__ out)
{
    const int row = blockIdx.x;
    const long long base = (long long)row * Hd;
    const int tid = threadIdx.x;

    float v[3];
    float s = 0.f, s2 = 0.f;
#pragma unroll
    for (int u = 0; u < 3; u++) {
        const int idx = tid + u * 256;
        const float val = X[base + idx] + Rres[base + idx];
        v[u] = val; s += val; s2 += val * val;
    }
#pragma unroll
    for (int off = 16; off >= 1; off >>= 1) {
        s  += __shfl_xor_sync(0xffffffffu, s, off);
        s2 += __shfl_xor_sync(0xffffffffu, s2, off);
    }
    __shared__ float ss[8], ss2[8], mv[2];
    const int wid = tid >> 5, lane = tid & 31;
    if (lane == 0) { ss[wid] = s; ss2[wid] = s2; }
    __syncthreads();
    if (tid == 0) {
        float S_ = 0.f, S2_ = 0.f;
        for (int w = 0; w < 8; w++) { S_ += ss[w]; S2_ += ss2[w]; }
        const float mean = S_ * (1.f / 768.f);
        const float var  = S2_ * (1.f / 768.f) - mean * mean;
        mv[0] = mean;
        mv[1] = rsqrtf(var + 1e-5f);
    }
    __syncthreads();
    const float mean = mv[0], rstd = mv[1];
#pragma unroll
    for (int u = 0; u < 3; u++) {
        const int idx = tid + u * 256;
        out[base + idx] = (v[u] - mean) * rstd * gam[idx] + bet[idx];
    }
}

// ---------------------------------------------------------------------------
// kernel_launch
// ---------------------------------------------------------------------------
#define SYM(v, s) cudaGetSymbolAddress((void**)&v, s)

extern "C" void kernel_launch(void* const* d_in, const int* in_sizes, int n_in,
                              void* d_out, int out_size)
{
    const float* hs      = (const float*)d_in[0];
    const int*   lang    = (const int*)  d_in[1];
    const float* Wq_lang = (const float*)d_in[3];
    const float* bq_lang = (const float*)d_in[4];
    const float* Wk_lang = (const float*)d_in[5];
    const float* bk_lang = (const float*)d_in[6];
    const float* in_w    = (const float*)d_in[7];
    const float* in_b    = (const float*)d_in[8];
    const float* out_w   = (const float*)d_in[9];
    const float* out_b   = (const float*)d_in[10];
    const float* alignT  = (const float*)d_in[11];
    const float* proj_w  = (const float*)d_in[12];
    const float* proj_b  = (const float*)d_in[13];
    const float* ln_g    = (const float*)d_in[14];
    const float* ln_b    = (const float*)d_in[15];
    float* out = (float*)d_out;

    float *Qp, *Kp, *Vp, *ctx, *obuf;
    SYM(Qp, g_Q); SYM(Kp, g_K); SYM(Vp, g_V); SYM(ctx, g_ctx); SYM(obuf, g_o);

    bf16 *hs_h, *hs_l, *ctx_h, *ctx_l;
    SYM(hs_h, g_hs_h);   SYM(hs_l, g_hs_l);
    SYM(ctx_h, g_ctx_h); SYM(ctx_l, g_ctx_l);

    bf16 *inw_h, *inw_l, *pw_h, *pw_l, *owT_h, *owT_l;
    SYM(inw_h, g_inw_h); SYM(inw_l, g_inw_l);
    SYM(pw_h, g_pw_h);   SYM(pw_l, g_pw_l);
    SYM(owT_h, g_owT_h); SYM(owT_l, g_owT_l);

    bf16 *WqT_h, *WqT_l, *WkT_h, *WkT_l, *Wqc_h, *Wqc_l, *Wkc_h, *Wkc_l;
    bf16 *GT_h, *GT_l, *WfT_h, *WfT_l, *scr_h, *scr_l;
    SYM(WqT_h, g_WqT_h); SYM(WqT_l, g_WqT_l);
    SYM(WkT_h, g_WkT_h); SYM(WkT_l, g_WkT_l);
    SYM(Wqc_h, g_Wqc_h); SYM(Wqc_l, g_Wqc_l);
    SYM(Wkc_h, g_Wkc_h); SYM(Wkc_l, g_Wkc_l);
    SYM(GT_h, g_GT_h);   SYM(GT_l, g_GT_l);
    SYM(WfT_h, g_WfT_h); SYM(WfT_l, g_WfT_l);
    SYM(scr_h, g_scr_h); SYM(scr_l, g_scr_l);

    float *bqc, *bkc, *bfin;
    SYM(bqc, g_bqc); SYM(bkc, g_bkc); SYM(bfin, g_bfin);

    bf16 *F_h, *F_l, *FT_h, *FT_l, *P1_h, *P1_l, *QT1_h, *QT1_l;
    bf16 *P2_h, *P2_l, *QT2_h, *QT2_l, *M_h, *M_l, *MT_h, *MT_l;
    SYM(F_h, g_F_h);   SYM(F_l, g_F_l);   SYM(FT_h, g_FT_h); SYM(FT_l, g_FT_l);
    SYM(P1_h, g_P1_h); SYM(P1_l, g_P1_l); SYM(QT1_h, g_QT1_h); SYM(QT1_l, g_QT1_l);
    SYM(P2_h, g_P2_h); SYM(P2_l, g_P2_l); SYM(QT2_h, g_QT2_h); SYM(QT2_l, g_QT2_l);
    SYM(M_h, g_M_h);   SYM(M_l, g_M_l);   SYM(MT_h, g_MT_h); SYM(MT_l, g_MT_l);

    unsigned char *fF, *fP1, *fP2;
    SYM(fF, g_fF); SYM(fP1, g_fP1); SYM(fP2, g_fP2);

    cudaFuncSetAttribute(k_final, cudaFuncAttributeMaxDynamicSharedMemorySize, GEMM_SMEM);
    cudaFuncSetAttribute(k_qkv,   cudaFuncAttributeMaxDynamicSharedMemorySize, GEMM_SMEM);
    cudaFuncSetAttribute(k_wcomb, cudaFuncAttributeMaxDynamicSharedMemorySize, GEMM_SMEM);
    cudaFuncSetAttribute(k_G,     cudaFuncAttributeMaxDynamicSharedMemorySize, GEMM_SMEM);
    cudaFuncSetAttribute(k_Wfin,  cudaFuncAttributeMaxDynamicSharedMemorySize, GEMM_SMEM);
    cudaFuncSetAttribute(tc_chain,cudaFuncAttributeMaxDynamicSharedMemorySize, GEMM_SMEM);

    const dim3 thr(256);

    // --- conversions ---
    k_conv<<<BS * Hd / 1024, thr>>>(hs, hs_h, hs_l);
    k_conv<<<(int)(3 * HH / 1024), thr>>>(in_w, inw_h, inw_l);
    k_conv<<<(int)(HH / 1024), thr>>>(proj_w, pw_h, pw_l);
    k_convT<<<dim3((int)(HH / 1024), 1), thr>>>(out_w, owT_h, owT_l);
    k_convT<<<dim3((int)(HH / 1024), NL), thr>>>(Wq_lang, WqT_h, WqT_l);
    k_convT<<<dim3((int)(HH / 1024), NL), thr>>>(Wk_lang, WkT_h, WkT_l);

    // --- weight combine (independent of hs) ---
    k_wcomb<<<dim3(6, 6, 2 * NL), thr, GEMM_SMEM>>>(
        inw_h, inw_l, WqT_h, WqT_l, WkT_h, WkT_l, Wqc_h, Wqc_l, Wkc_h, Wkc_l);
    k_bias_qk<<<dim3(2, NL), Hd>>>(in_w, in_b, bq_lang, bk_lang, bqc, bkc);

    // --- chain -> M ---
    k_flags<<<1, 32>>>(lang, fF, fP1, fP2);
    k_factors<<<dim3((int)(HH / 1024), NL * 8), thr>>>(alignT, lang, F_h, F_l, FT_h, FT_l);
    tc_chain<<<dim3(6, 6, NL * 4), thr, GEMM_SMEM>>>(F_h, F_l, FT_h, FT_l, fF,
                                                     P1_h, P1_l, QT1_h, QT1_l, 8, 4);
    tc_chain<<<dim3(6, 6, NL * 2), thr, GEMM_SMEM>>>(P1_h, P1_l, QT1_h, QT1_l, fP1,
                                                     P2_h, P2_l, QT2_h, QT2_l, 4, 2);
    tc_chain<<<dim3(6, 6, NL), thr, GEMM_SMEM>>>(P2_h, P2_l, QT2_h, QT2_l, fP2,
                                                 M_h, M_l, MT_h, MT_l, 2, 1);

    // --- G = M @ proj_w^T ; Wfin = out_w^T @ G ; bfin ---
    k_G<<<dim3(6, 6, NL), thr, GEMM_SMEM>>>(M_h, M_l, pw_h, pw_l,
                                            scr_h, scr_l, GT_h, GT_l);
    k_Wfin<<<dim3(6, 6, NL), thr, GEMM_SMEM>>>(owT_h, owT_l, GT_h, GT_l,
                                               scr_h, scr_l, WfT_h, WfT_l);
    k_bias_fin<<<NL, Hd>>>(GT_h, GT_l, out_b, proj_b, bfin);

    // --- fused QKV ---
    k_qkv<<<dim3(6, 6, 24), thr, GEMM_SMEM>>>(
        hs_h, hs_l, Wqc_h, Wqc_l, bqc, Wkc_h, Wkc_l, bkc,
        inw_h + 2 * HH, inw_l + 2 * HH, in_b + 2 * Hd, lang, Qp, Kp, Vp);

    // --- attention ---
    k_attn<<<dim3(S / 64, NH, Bsz), thr>>>(Qp, Kp, Vp, ctx);
    k_conv<<<BS * Hd / 1024, thr>>>(ctx, ctx_h, ctx_l);

    // --- fused out_proj @ M @ proj ---
    k_final<<<dim3(6, 6, Bsz), thr, GEMM_SMEM>>>(ctx_h, ctx_l, WfT_h, WfT_l,
                                                 bfin, lang, obuf);

    // --- residual + LayerNorm ---
    k_ln<<<BS, thr>>>(obuf, hs, ln_g, ln_b, out);
}